// round 1
// baseline (speedup 1.0000x reference)
#include <cuda_runtime.h>
#include <math.h>

// Problem constants
#define BB 4
#define SS 2048
#define DD 1024

// Scratch (allocation-free rule: __device__ globals)
__device__ float g_Qp[(size_t)BB * SS * DD];      // 32 MB
__device__ float g_Kp[(size_t)BB * SS * DD];      // 32 MB
__device__ float g_Vp[(size_t)BB * SS * DD];      // 32 MB
__device__ float g_Sc[(size_t)BB * SS * SS];      // 64 MB

// ---------------------------------------------------------------------------
// Tiled fp32 GEMM: C = alpha * A @ op(B) (+ bias)
//   A: [M, K] row-major
//   B: TRANS_B ? [N, K] row-major : [K, N] row-major
//   blockDim = 256, tile 128x128x16, 8x8 per-thread micro-tile
//   blockIdx.z = batch with byte-free element strides sAz/sBz/sCz
// ---------------------------------------------------------------------------
template <bool TRANS_B, bool HAS_BIAS>
__global__ __launch_bounds__(256, 2)
void gemm128(const float* __restrict__ A, const float* __restrict__ B,
             const float* __restrict__ bias, float* __restrict__ C,
             int M, int N, int K, float alpha,
             long sAz, long sBz, long sCz)
{
    const int BM = 128, BN = 128, BK = 16;
    __shared__ float As[BK][BM + 4];
    __shared__ float Bs[BK][BN + 4];

    const float* Ab = A + (long)blockIdx.z * sAz;
    const float* Bb = B + (long)blockIdx.z * sBz;
    float*       Cb = C + (long)blockIdx.z * sCz;

    const int tid = threadIdx.x;
    const int m0 = blockIdx.y * BM;
    const int n0 = blockIdx.x * BN;

    // A-style (row-major along K) loader indices: 128 rows x 16 k, 2 float4/thread
    const int lr = tid >> 2;           // 0..63
    const int lk = (tid & 3) * 4;      // 0,4,8,12

    // NN B loader indices: 16 k-rows x 128 n, 2 float4/thread
    const int bkr = tid >> 5;          // 0..7
    const int bnc = (tid & 31) * 4;    // 0..124

    // Compute mapping: 8 warps as 4(m) x 2(n); warp tile 32x64; lane 4x8
    const int warp = tid >> 5;
    const int lane = tid & 31;
    const int tm = (warp >> 1) * 32 + (lane & 3) * 8;
    const int tn = (warp & 1) * 64 + (lane >> 2) * 8;

    float acc[8][8];
#pragma unroll
    for (int i = 0; i < 8; i++)
#pragma unroll
        for (int j = 0; j < 8; j++) acc[i][j] = 0.0f;

    for (int k0 = 0; k0 < K; k0 += BK) {
        // ---- load A tile (transpose into As[k][m]) ----
#pragma unroll
        for (int r = 0; r < 2; r++) {
            const int row = lr + r * 64;
            float4 v = *(const float4*)(Ab + (long)(m0 + row) * K + k0 + lk);
            As[lk + 0][row] = v.x;
            As[lk + 1][row] = v.y;
            As[lk + 2][row] = v.z;
            As[lk + 3][row] = v.w;
        }
        // ---- load B tile into Bs[k][n] ----
        if (TRANS_B) {
#pragma unroll
            for (int r = 0; r < 2; r++) {
                const int row = lr + r * 64;   // n index
                float4 v = *(const float4*)(Bb + (long)(n0 + row) * K + k0 + lk);
                Bs[lk + 0][row] = v.x;
                Bs[lk + 1][row] = v.y;
                Bs[lk + 2][row] = v.z;
                Bs[lk + 3][row] = v.w;
            }
        } else {
#pragma unroll
            for (int r = 0; r < 2; r++) {
                const int kr = bkr + r * 8;
                float4 v = *(const float4*)(Bb + (long)(k0 + kr) * N + n0 + bnc);
                *(float4*)&Bs[kr][bnc] = v;
            }
        }
        __syncthreads();

        // ---- 16 k-steps of 8x8 outer product ----
#pragma unroll
        for (int kk = 0; kk < BK; kk++) {
            float a[8], b[8];
            *(float4*)&a[0] = *(const float4*)&As[kk][tm];
            *(float4*)&a[4] = *(const float4*)&As[kk][tm + 4];
            *(float4*)&b[0] = *(const float4*)&Bs[kk][tn];
            *(float4*)&b[4] = *(const float4*)&Bs[kk][tn + 4];
#pragma unroll
            for (int i = 0; i < 8; i++)
#pragma unroll
                for (int j = 0; j < 8; j++)
                    acc[i][j] = fmaf(a[i], b[j], acc[i][j]);
        }
        __syncthreads();
    }

    // ---- epilogue ----
#pragma unroll
    for (int i = 0; i < 8; i++) {
        const long m = m0 + tm + i;
#pragma unroll
        for (int j = 0; j < 8; j += 4) {
            float4 o;
            o.x = acc[i][j + 0] * alpha;
            o.y = acc[i][j + 1] * alpha;
            o.z = acc[i][j + 2] * alpha;
            o.w = acc[i][j + 3] * alpha;
            if (HAS_BIAS) {
                const int nb = n0 + tn + j;
                o.x += bias[nb + 0];
                o.y += bias[nb + 1];
                o.z += bias[nb + 2];
                o.w += bias[nb + 3];
            }
            *(float4*)(Cb + m * N + n0 + tn + j) = o;
        }
    }
}

// ---------------------------------------------------------------------------
// Row softmax over 2048 columns, in place. One block (256 threads) per row.
// ---------------------------------------------------------------------------
__global__ __launch_bounds__(256)
void softmax2048(float* __restrict__ S)
{
    float* row = S + (long)blockIdx.x * SS;
    const int t = threadIdx.x;

    float v[8];
    float mx = -1e30f;
#pragma unroll
    for (int i = 0; i < 8; i++) {
        v[i] = row[t + i * 256];
        mx = fmaxf(mx, v[i]);
    }
#pragma unroll
    for (int o = 16; o > 0; o >>= 1)
        mx = fmaxf(mx, __shfl_xor_sync(0xFFFFFFFFu, mx, o));

    __shared__ float red[8];
    if ((t & 31) == 0) red[t >> 5] = mx;
    __syncthreads();
    float bmax = red[0];
#pragma unroll
    for (int i = 1; i < 8; i++) bmax = fmaxf(bmax, red[i]);
    __syncthreads();

    float sum = 0.0f;
#pragma unroll
    for (int i = 0; i < 8; i++) {
        v[i] = __expf(v[i] - bmax);
        sum += v[i];
    }
#pragma unroll
    for (int o = 16; o > 0; o >>= 1)
        sum += __shfl_xor_sync(0xFFFFFFFFu, sum, o);
    if ((t & 31) == 0) red[t >> 5] = sum;
    __syncthreads();
    float tot = 0.0f;
#pragma unroll
    for (int i = 0; i < 8; i++) tot += red[i];

    const float inv = __frcp_rn(tot);
#pragma unroll
    for (int i = 0; i < 8; i++)
        row[t + i * 256] = v[i] * inv;
}

// ---------------------------------------------------------------------------
// Launch
// ---------------------------------------------------------------------------
extern "C" void kernel_launch(void* const* d_in, const int* in_sizes, int n_in,
                              void* d_out, int out_size)
{
    const float* q  = (const float*)d_in[0];
    const float* k  = (const float*)d_in[1];
    const float* v  = (const float*)d_in[2];
    const float* Wq = (const float*)d_in[3];
    const float* bq = (const float*)d_in[4];
    const float* Wk = (const float*)d_in[5];
    const float* bk = (const float*)d_in[6];
    const float* Wv = (const float*)d_in[7];
    const float* bv = (const float*)d_in[8];
    float* out = (float*)d_out;

    float *Qp, *Kp, *Vp, *Sc;
    cudaGetSymbolAddress((void**)&Qp, g_Qp);
    cudaGetSymbolAddress((void**)&Kp, g_Kp);
    cudaGetSymbolAddress((void**)&Vp, g_Vp);
    cudaGetSymbolAddress((void**)&Sc, g_Sc);

    const dim3 blk(256);

    // 1) Projections: M = B*S = 8192, N = D = 1024, K = D = 1024
    {
        dim3 g(DD / 128, (BB * SS) / 128, 1);   // (8, 64)
        gemm128<false, true><<<g, blk>>>(q, Wq, bq, Qp, BB * SS, DD, DD, 1.0f, 0, 0, 0);
        gemm128<false, true><<<g, blk>>>(k, Wk, bk, Kp, BB * SS, DD, DD, 1.0f, 0, 0, 0);
        gemm128<false, true><<<g, blk>>>(v, Wv, bv, Vp, BB * SS, DD, DD, 1.0f, 0, 0, 0);
    }

    // 2) Scores: per batch, S[m,n] = (1/32) * Qp[m,:] . Kp[n,:]
    {
        dim3 g(SS / 128, SS / 128, BB);         // (16, 16, 4)
        gemm128<true, false><<<g, blk>>>(Qp, Kp, nullptr, Sc,
                                         SS, SS, DD, 0.03125f,
                                         (long)SS * DD, (long)SS * DD, (long)SS * SS);
    }

    // 3) Softmax over rows (B*S rows of length S)
    softmax2048<<<BB * SS, blk>>>(Sc);

    // 4) Output: per batch, O = W @ Vp   (M=S, N=D, K=S)
    {
        dim3 g(DD / 128, SS / 128, BB);         // (8, 16, 4)
        gemm128<false, false><<<g, blk>>>(Sc, Vp, nullptr, out,
                                          SS, DD, SS, 1.0f,
                                          (long)SS * SS, (long)SS * DD, (long)SS * DD);
    }
}

// round 3
// speedup vs baseline: 2.0040x; 2.0040x over previous
#include <cuda_runtime.h>
#include <cstdint>
#include <math.h>

#define BB 4
#define SS 2048
#define DD 1024

// Scratch (__device__ globals — allocation-free rule)
__device__ float g_Qp[(size_t)BB * SS * DD];
__device__ float g_Kp[(size_t)BB * SS * DD];
__device__ float g_Vp[(size_t)BB * SS * DD];
__device__ float g_Sc[(size_t)BB * SS * SS];
__device__ float g_rq[(size_t)BB * SS * DD];
__device__ float g_rk[(size_t)BB * SS * DD];
__device__ float g_rv[(size_t)BB * SS * DD];
__device__ float g_rWq[(size_t)DD * DD];
__device__ float g_rWk[(size_t)DD * DD];
__device__ float g_rWv[(size_t)DD * DD];

__device__ __forceinline__ float to_tf32(float x) {
    float y;
    asm("cvt.rna.tf32.f32 %0, %1;" : "=f"(y) : "f"(x));
    return y;
}

__device__ __forceinline__ void cp16(uint32_t dst, const void* src) {
    asm volatile("cp.async.cg.shared.global [%0], [%1], 16;" :: "r"(dst), "l"(src));
}
__device__ __forceinline__ void cp_commit() {
    asm volatile("cp.async.commit_group;");
}

__device__ __forceinline__ void mma_tf32(float* c, const uint32_t* a, const uint32_t* b) {
    asm volatile(
        "mma.sync.aligned.m16n8k8.row.col.f32.tf32.tf32.f32 "
        "{%0,%1,%2,%3}, {%4,%5,%6,%7}, {%8,%9}, {%0,%1,%2,%3};"
        : "+f"(c[0]), "+f"(c[1]), "+f"(c[2]), "+f"(c[3])
        : "r"(a[0]), "r"(a[1]), "r"(a[2]), "r"(a[3]), "r"(b[0]), "r"(b[1]));
}

// ---------------------------------------------------------------------------
// Elementwise round fp32 -> tf32(rna), stored as fp32
// ---------------------------------------------------------------------------
__global__ __launch_bounds__(256)
void round_tf32_kernel(const float* __restrict__ in, float* __restrict__ out, long n4)
{
    long i = (long)blockIdx.x * blockDim.x + threadIdx.x;
    long stride = (long)gridDim.x * blockDim.x;
    for (; i < n4; i += stride) {
        float4 v = ((const float4*)in)[i];
        v.x = to_tf32(v.x); v.y = to_tf32(v.y);
        v.z = to_tf32(v.z); v.w = to_tf32(v.w);
        ((float4*)out)[i] = v;
    }
}

// ---------------------------------------------------------------------------
// TF32 tensor-core GEMM: C = alpha * A @ op(B) (+ bias)
//   A: [M,K] row-major.  B: TRANS_B ? [N,K] : [K,N] row-major.
//   128 threads, tile 128x128x16, 4 warps of 64x64, double-buffered cp.async.
// ---------------------------------------------------------------------------
template <bool TRANS_B, bool HAS_BIAS, bool ROUND_OUT>
__global__ __launch_bounds__(128, 2)
void mmagemm(const float* __restrict__ A, const float* __restrict__ B,
             const float* __restrict__ bias, float* __restrict__ C,
             int M, int N, int K, float alpha,
             long sAz, long sBz, long sCz)
{
    constexpr int BM = 128, BN = 128, BK = 16;
    constexpr int AST = 20;                      // A smem row stride (floats)
    constexpr int BST = TRANS_B ? 20 : 136;      // B smem row stride
    constexpr int BSZ = TRANS_B ? BN * 20 : BK * 136;

    __shared__ float As[2][BM * AST];
    __shared__ float Bs[2][BSZ];

    const float* Ab = A + (long)blockIdx.z * sAz;
    const float* Bb = B + (long)blockIdx.z * sBz;
    float*       Cb = C + (long)blockIdx.z * sCz;

    const int tid  = threadIdx.x;
    const int lane = tid & 31;
    const int warp = tid >> 5;
    const int m0 = blockIdx.y * BM;
    const int n0 = blockIdx.x * BN;

    const int wm = (warp >> 1) * 64;
    const int wn = (warp & 1) * 64;
    const int r  = lane >> 2;      // groupID
    const int cc = lane & 3;       // threadID_in_group

    uint32_t aBase[2], bBase[2];
#pragma unroll
    for (int s = 0; s < 2; s++) {
        aBase[s] = (uint32_t)__cvta_generic_to_shared(&As[s][0]);
        bBase[s] = (uint32_t)__cvta_generic_to_shared(&Bs[s][0]);
    }

    // loaders: A tile: thread tid handles row tid, 4x 16B chunks along k
    const int bkr = tid >> 3;            // NN B: k-row 0..15
    const int bnc = (tid & 7) * 16;      // NN B: n start (16 floats)

    auto load_tiles = [&](int buf, int k0) {
#pragma unroll
        for (int c = 0; c < 4; c++) {
            cp16(aBase[buf] + (uint32_t)(tid * AST + 4 * c) * 4,
                 Ab + (long)(m0 + tid) * K + k0 + 4 * c);
        }
        if (TRANS_B) {
#pragma unroll
            for (int c = 0; c < 4; c++) {
                cp16(bBase[buf] + (uint32_t)(tid * BST + 4 * c) * 4,
                     Bb + (long)(n0 + tid) * K + k0 + 4 * c);
            }
        } else {
#pragma unroll
            for (int c = 0; c < 4; c++) {
                cp16(bBase[buf] + (uint32_t)(bkr * BST + bnc + 4 * c) * 4,
                     Bb + (long)(k0 + bkr) * N + n0 + bnc + 4 * c);
            }
        }
    };

    float acc[4][8][4];
#pragma unroll
    for (int mt = 0; mt < 4; mt++)
#pragma unroll
        for (int nt = 0; nt < 8; nt++)
#pragma unroll
            for (int i = 0; i < 4; i++) acc[mt][nt][i] = 0.0f;

    const int KT = K / BK;
    load_tiles(0, 0);
    cp_commit();

    for (int kt = 0; kt < KT; kt++) {
        const int buf = kt & 1;
        if (kt + 1 < KT) {
            load_tiles((kt + 1) & 1, (kt + 1) * BK);
            cp_commit();
            asm volatile("cp.async.wait_group 1;");
        } else {
            asm volatile("cp.async.wait_group 0;");
        }
        __syncthreads();

        const float* as = As[buf];
        const float* bs = Bs[buf];
#pragma unroll
        for (int ks = 0; ks < 2; ks++) {
            const int k8 = ks * 8;
            uint32_t afr[4][4];
#pragma unroll
            for (int mt = 0; mt < 4; mt++) {
                const int rm = wm + mt * 16;
                afr[mt][0] = __float_as_uint(as[(rm + r)     * AST + k8 + cc]);
                afr[mt][1] = __float_as_uint(as[(rm + r + 8) * AST + k8 + cc]);
                afr[mt][2] = __float_as_uint(as[(rm + r)     * AST + k8 + cc + 4]);
                afr[mt][3] = __float_as_uint(as[(rm + r + 8) * AST + k8 + cc + 4]);
            }
            uint32_t bfr[8][2];
#pragma unroll
            for (int nt = 0; nt < 8; nt++) {
                const int n = wn + nt * 8;
                if (TRANS_B) {
                    bfr[nt][0] = __float_as_uint(bs[(n + r) * BST + k8 + cc]);
                    bfr[nt][1] = __float_as_uint(bs[(n + r) * BST + k8 + cc + 4]);
                } else {
                    bfr[nt][0] = __float_as_uint(bs[(k8 + cc)     * BST + n + r]);
                    bfr[nt][1] = __float_as_uint(bs[(k8 + cc + 4) * BST + n + r]);
                }
            }
#pragma unroll
            for (int mt = 0; mt < 4; mt++)
#pragma unroll
                for (int nt = 0; nt < 8; nt++)
                    mma_tf32(acc[mt][nt], afr[mt], bfr[nt]);
        }
        __syncthreads();
    }

    // epilogue
#pragma unroll
    for (int mt = 0; mt < 4; mt++) {
        const long row0 = m0 + wm + mt * 16 + r;
#pragma unroll
        for (int nt = 0; nt < 8; nt++) {
            const int colb = n0 + wn + nt * 8 + 2 * cc;
            float2 v0, v1;
            v0.x = acc[mt][nt][0] * alpha; v0.y = acc[mt][nt][1] * alpha;
            v1.x = acc[mt][nt][2] * alpha; v1.y = acc[mt][nt][3] * alpha;
            if (HAS_BIAS) {
                v0.x += bias[colb]; v0.y += bias[colb + 1];
                v1.x += bias[colb]; v1.y += bias[colb + 1];
            }
            if (ROUND_OUT) {
                v0.x = to_tf32(v0.x); v0.y = to_tf32(v0.y);
                v1.x = to_tf32(v1.x); v1.y = to_tf32(v1.y);
            }
            *(float2*)(Cb + row0 * N + colb)       = v0;
            *(float2*)(Cb + (row0 + 8) * N + colb) = v1;
        }
    }
}

// ---------------------------------------------------------------------------
// Row softmax over 2048 cols, in place; outputs rounded to tf32(rna).
// ---------------------------------------------------------------------------
__global__ __launch_bounds__(256)
void softmax2048(float* __restrict__ S)
{
    float* row = S + (long)blockIdx.x * SS;
    const int t = threadIdx.x;

    float v[8];
    float mx = -1e30f;
#pragma unroll
    for (int i = 0; i < 8; i++) {
        v[i] = row[t + i * 256];
        mx = fmaxf(mx, v[i]);
    }
#pragma unroll
    for (int o = 16; o > 0; o >>= 1)
        mx = fmaxf(mx, __shfl_xor_sync(0xFFFFFFFFu, mx, o));

    __shared__ float red[8];
    if ((t & 31) == 0) red[t >> 5] = mx;
    __syncthreads();
    float bmax = red[0];
#pragma unroll
    for (int i = 1; i < 8; i++) bmax = fmaxf(bmax, red[i]);
    __syncthreads();

    float sum = 0.0f;
#pragma unroll
    for (int i = 0; i < 8; i++) {
        v[i] = __expf(v[i] - bmax);
        sum += v[i];
    }
#pragma unroll
    for (int o = 16; o > 0; o >>= 1)
        sum += __shfl_xor_sync(0xFFFFFFFFu, sum, o);
    if ((t & 31) == 0) red[t >> 5] = sum;
    __syncthreads();
    float tot = 0.0f;
#pragma unroll
    for (int i = 0; i < 8; i++) tot += red[i];

    const float inv = __frcp_rn(tot);
#pragma unroll
    for (int i = 0; i < 8; i++)
        row[t + i * 256] = to_tf32(v[i] * inv);
}

// ---------------------------------------------------------------------------
extern "C" void kernel_launch(void* const* d_in, const int* in_sizes, int n_in,
                              void* d_out, int out_size)
{
    const float* q  = (const float*)d_in[0];
    const float* k  = (const float*)d_in[1];
    const float* v  = (const float*)d_in[2];
    const float* Wq = (const float*)d_in[3];
    const float* bq = (const float*)d_in[4];
    const float* Wk = (const float*)d_in[5];
    const float* bk = (const float*)d_in[6];
    const float* Wv = (const float*)d_in[7];
    const float* bv = (const float*)d_in[8];
    float* out = (float*)d_out;

    float *Qp, *Kp, *Vp, *Sc, *rq, *rk, *rv, *rWq, *rWk, *rWv;
    cudaGetSymbolAddress((void**)&Qp, g_Qp);
    cudaGetSymbolAddress((void**)&Kp, g_Kp);
    cudaGetSymbolAddress((void**)&Vp, g_Vp);
    cudaGetSymbolAddress((void**)&Sc, g_Sc);
    cudaGetSymbolAddress((void**)&rq, g_rq);
    cudaGetSymbolAddress((void**)&rk, g_rk);
    cudaGetSymbolAddress((void**)&rv, g_rv);
    cudaGetSymbolAddress((void**)&rWq, g_rWq);
    cudaGetSymbolAddress((void**)&rWk, g_rWk);
    cudaGetSymbolAddress((void**)&rWv, g_rWv);

    const long nQKV = (long)BB * SS * DD;
    const long nW   = (long)DD * DD;

    // 0) rna-round all GEMM operands to tf32
    round_tf32_kernel<<<2048, 256>>>(q,  rq,  nQKV / 4);
    round_tf32_kernel<<<2048, 256>>>(k,  rk,  nQKV / 4);
    round_tf32_kernel<<<2048, 256>>>(v,  rv,  nQKV / 4);
    round_tf32_kernel<<<512,  256>>>(Wq, rWq, nW / 4);
    round_tf32_kernel<<<512,  256>>>(Wk, rWk, nW / 4);
    round_tf32_kernel<<<512,  256>>>(Wv, rWv, nW / 4);

    const dim3 blk(128);

    // 1) Projections: M=8192, N=1024, K=1024 (NN, bias, round outputs)
    {
        dim3 g(DD / 128, (BB * SS) / 128, 1);
        mmagemm<false, true, true><<<g, blk>>>(rq, rWq, bq, Qp, BB * SS, DD, DD, 1.0f, 0, 0, 0);
        mmagemm<false, true, true><<<g, blk>>>(rk, rWk, bk, Kp, BB * SS, DD, DD, 1.0f, 0, 0, 0);
        mmagemm<false, true, true><<<g, blk>>>(rv, rWv, bv, Vp, BB * SS, DD, DD, 1.0f, 0, 0, 0);
    }

    // 2) Scores: S = (1/32) Qp @ Kp^T per batch (TN)
    {
        dim3 g(SS / 128, SS / 128, BB);
        mmagemm<true, false, false><<<g, blk>>>(Qp, Kp, nullptr, Sc,
                                                SS, SS, DD, 0.03125f,
                                                (long)SS * DD, (long)SS * DD, (long)SS * SS);
    }

    // 3) Softmax (rounds outputs to tf32)
    softmax2048<<<BB * SS, 256>>>(Sc);

    // 4) O = W @ Vp per batch (NN): M=2048, N=1024, K=2048
    {
        dim3 g(DD / 128, SS / 128, BB);
        mmagemm<false, false, false><<<g, blk>>>(Sc, Vp, nullptr, out,
                                                 SS, DD, SS, 1.0f,
                                                 (long)SS * SS, (long)SS * DD, (long)SS * DD);
    }
}

// round 5
// speedup vs baseline: 2.0640x; 1.0299x over previous
#include <cuda_runtime.h>
#include <cstdint>
#include <math.h>

#define BB 4
#define SS 2048
#define DD 1024

// Scratch (__device__ globals — allocation-free rule)
__device__ float g_Qp[(size_t)BB * SS * DD];
__device__ float g_Kp[(size_t)BB * SS * DD];
__device__ float g_Vp[(size_t)BB * SS * DD];
__device__ float g_Sc[(size_t)BB * SS * SS];
__device__ float g_rq[(size_t)BB * SS * DD];
__device__ float g_rk[(size_t)BB * SS * DD];
__device__ float g_rv[(size_t)BB * SS * DD];
__device__ float g_rWq[(size_t)DD * DD];
__device__ float g_rWk[(size_t)DD * DD];
__device__ float g_rWv[(size_t)DD * DD];

__device__ __forceinline__ float to_tf32(float x) {
    float y;
    asm("cvt.rna.tf32.f32 %0, %1;" : "=f"(y) : "f"(x));
    return y;
}
__device__ __forceinline__ void cp16(uint32_t dst, const void* src) {
    asm volatile("cp.async.cg.shared.global [%0], [%1], 16;" :: "r"(dst), "l"(src));
}
__device__ __forceinline__ void cp_commit() {
    asm volatile("cp.async.commit_group;");
}
__device__ __forceinline__ void mma_tf32(float* c, const uint32_t* a, const uint32_t* b) {
    asm volatile(
        "mma.sync.aligned.m16n8k8.row.col.f32.tf32.tf32.f32 "
        "{%0,%1,%2,%3}, {%4,%5,%6,%7}, {%8,%9}, {%0,%1,%2,%3};"
        : "+f"(c[0]), "+f"(c[1]), "+f"(c[2]), "+f"(c[3])
        : "r"(a[0]), "r"(a[1]), "r"(a[2]), "r"(a[3]), "r"(b[0]), "r"(b[1]));
}

// ---------------------------------------------------------------------------
// Elementwise round fp32 -> tf32(rna)
// ---------------------------------------------------------------------------
__global__ __launch_bounds__(256)
void round_tf32_kernel(const float* __restrict__ in, float* __restrict__ out, long n4)
{
    long i = (long)blockIdx.x * blockDim.x + threadIdx.x;
    long stride = (long)gridDim.x * blockDim.x;
    for (; i < n4; i += stride) {
        float4 v = ((const float4*)in)[i];
        v.x = to_tf32(v.x); v.y = to_tf32(v.y);
        v.z = to_tf32(v.z); v.w = to_tf32(v.w);
        ((float4*)out)[i] = v;
    }
}

// ---------------------------------------------------------------------------
// TF32 tensor-core GEMM: C = alpha * A @ op(B) (+ bias)
//   A: [M,K] row-major.  B: TRANS_B ? [N,K] : [K,N] row-major.
//   256 threads, tile 128x128x32, 8 warps (2m x 4n, warp tile 64x32),
//   3-stage cp.async pipeline.
// ---------------------------------------------------------------------------
#define STAGES 3

template <bool TRANS_B>
struct SmemCfg {
    static constexpr int AST = 36;                           // A row stride (floats)
    static constexpr int BST = TRANS_B ? 36 : 132;           // B row stride
    static constexpr int A_FLOATS = 128 * 36;                // 4608
    static constexpr int B_FLOATS = TRANS_B ? 128 * 36 : 32 * 132;
    static constexpr int STAGE_FLOATS = A_FLOATS + B_FLOATS;
    static constexpr int SMEM_BYTES = STAGES * STAGE_FLOATS * 4;
};

template <bool TRANS_B, bool HAS_BIAS, bool ROUND_OUT>
__global__ __launch_bounds__(256, 2)
void mmagemm(const float* __restrict__ A, const float* __restrict__ B,
             const float* __restrict__ bias, float* __restrict__ C,
             int M, int N, int K, float alpha,
             long sAz, long sBz, long sCz)
{
    using CFG = SmemCfg<TRANS_B>;
    constexpr int BK = 32;
    constexpr int AST = CFG::AST;
    constexpr int BST = CFG::BST;

    extern __shared__ float sm[];

    const float* Ab = A + (long)blockIdx.z * sAz;
    const float* Bb = B + (long)blockIdx.z * sBz;
    float*       Cb = C + (long)blockIdx.z * sCz;

    const int tid  = threadIdx.x;
    const int lane = tid & 31;
    const int warp = tid >> 5;
    const int m0 = blockIdx.y * 128;
    const int n0 = blockIdx.x * 128;

    // 8 warps: 2(m) x 4(n); warp tile 64x32
    const int wm = (warp >> 2) * 64;
    const int wn = (warp & 3) * 32;
    const int r  = lane >> 2;      // groupID 0..7
    const int cc = lane & 3;       // thread-in-group 0..3

    uint32_t smBase = (uint32_t)__cvta_generic_to_shared(sm);

    // A loader: thread t -> row t>>1 (0..127), float col (t&1)*16 + 4i
    const int arow = tid >> 1;
    const int acol = (tid & 1) * 16;
    // NN B loader: thread t -> k-row t>>3 (0..31), float col (t&7)*16 + 4i
    const int bkr = tid >> 3;
    const int bnc = (tid & 7) * 16;

    auto load_tiles = [&](int stage, int k0) {
        const uint32_t aS = smBase + (uint32_t)(stage * CFG::STAGE_FLOATS) * 4u;
        const uint32_t bS = aS + (uint32_t)CFG::A_FLOATS * 4u;
#pragma unroll
        for (int i = 0; i < 4; i++) {
            cp16(aS + (uint32_t)(arow * AST + acol + 4 * i) * 4u,
                 Ab + (long)(m0 + arow) * K + k0 + acol + 4 * i);
        }
        if (TRANS_B) {
#pragma unroll
            for (int i = 0; i < 4; i++) {
                cp16(bS + (uint32_t)(arow * BST + acol + 4 * i) * 4u,
                     Bb + (long)(n0 + arow) * K + k0 + acol + 4 * i);
            }
        } else {
#pragma unroll
            for (int i = 0; i < 4; i++) {
                cp16(bS + (uint32_t)(bkr * BST + bnc + 4 * i) * 4u,
                     Bb + (long)(k0 + bkr) * N + n0 + bnc + 4 * i);
            }
        }
    };

    float acc[4][4][4];
#pragma unroll
    for (int mt = 0; mt < 4; mt++)
#pragma unroll
        for (int nt = 0; nt < 4; nt++)
#pragma unroll
            for (int i = 0; i < 4; i++) acc[mt][nt][i] = 0.0f;

    const int KT = K / BK;
#pragma unroll
    for (int s = 0; s < STAGES; s++) {
        if (s < KT) { load_tiles(s, s * BK); cp_commit(); }
    }

    for (int t = 0; t < KT; t++) {
        const int rem = KT - 1 - t;
        if (rem >= 2)      asm volatile("cp.async.wait_group 2;");
        else if (rem == 1) asm volatile("cp.async.wait_group 1;");
        else               asm volatile("cp.async.wait_group 0;");
        __syncthreads();

        const int stage = t % STAGES;
        const float* as = sm + stage * CFG::STAGE_FLOATS;
        const float* bs = as + CFG::A_FLOATS;

#pragma unroll
        for (int ks = 0; ks < 4; ks++) {
            const int k8 = ks * 8;
            uint32_t afr[4][4];
#pragma unroll
            for (int mt = 0; mt < 4; mt++) {
                const int rm = wm + mt * 16;
                afr[mt][0] = __float_as_uint(as[(rm + r)     * AST + k8 + cc]);
                afr[mt][1] = __float_as_uint(as[(rm + r + 8) * AST + k8 + cc]);
                afr[mt][2] = __float_as_uint(as[(rm + r)     * AST + k8 + cc + 4]);
                afr[mt][3] = __float_as_uint(as[(rm + r + 8) * AST + k8 + cc + 4]);
            }
            uint32_t bfr[4][2];
#pragma unroll
            for (int nt = 0; nt < 4; nt++) {
                const int n = wn + nt * 8;
                if (TRANS_B) {
                    bfr[nt][0] = __float_as_uint(bs[(n + r) * BST + k8 + cc]);
                    bfr[nt][1] = __float_as_uint(bs[(n + r) * BST + k8 + cc + 4]);
                } else {
                    bfr[nt][0] = __float_as_uint(bs[(k8 + cc)     * BST + n + r]);
                    bfr[nt][1] = __float_as_uint(bs[(k8 + cc + 4) * BST + n + r]);
                }
            }
#pragma unroll
            for (int mt = 0; mt < 4; mt++)
#pragma unroll
                for (int nt = 0; nt < 4; nt++)
                    mma_tf32(acc[mt][nt], afr[mt], bfr[nt]);
        }
        __syncthreads();

        if (t + STAGES < KT) { load_tiles(stage, (t + STAGES) * BK); cp_commit(); }
    }

    // epilogue
#pragma unroll
    for (int mt = 0; mt < 4; mt++) {
        const long row0 = m0 + wm + mt * 16 + r;
#pragma unroll
        for (int nt = 0; nt < 4; nt++) {
            const int colb = n0 + wn + nt * 8 + 2 * cc;
            float2 v0, v1;
            v0.x = acc[mt][nt][0] * alpha; v0.y = acc[mt][nt][1] * alpha;
            v1.x = acc[mt][nt][2] * alpha; v1.y = acc[mt][nt][3] * alpha;
            if (HAS_BIAS) {
                v0.x += bias[colb]; v0.y += bias[colb + 1];
                v1.x += bias[colb]; v1.y += bias[colb + 1];
            }
            if (ROUND_OUT) {
                v0.x = to_tf32(v0.x); v0.y = to_tf32(v0.y);
                v1.x = to_tf32(v1.x); v1.y = to_tf32(v1.y);
            }
            *(float2*)(Cb + row0 * N + colb)       = v0;
            *(float2*)(Cb + (row0 + 8) * N + colb) = v1;
        }
    }
}

// ---------------------------------------------------------------------------
// Row softmax over 2048 cols, in place; outputs rounded to tf32(rna).
// ---------------------------------------------------------------------------
__global__ __launch_bounds__(256)
void softmax2048(float* __restrict__ S)
{
    float* row = S + (long)blockIdx.x * SS;
    const int t = threadIdx.x;

    float v[8];
    float mx = -1e30f;
#pragma unroll
    for (int i = 0; i < 8; i++) {
        v[i] = row[t + i * 256];
        mx = fmaxf(mx, v[i]);
    }
#pragma unroll
    for (int o = 16; o > 0; o >>= 1)
        mx = fmaxf(mx, __shfl_xor_sync(0xFFFFFFFFu, mx, o));

    __shared__ float red[8];
    if ((t & 31) == 0) red[t >> 5] = mx;
    __syncthreads();
    float bmax = red[0];
#pragma unroll
    for (int i = 1; i < 8; i++) bmax = fmaxf(bmax, red[i]);
    __syncthreads();

    float sum = 0.0f;
#pragma unroll
    for (int i = 0; i < 8; i++) {
        v[i] = __expf(v[i] - bmax);
        sum += v[i];
    }
#pragma unroll
    for (int o = 16; o > 0; o >>= 1)
        sum += __shfl_xor_sync(0xFFFFFFFFu, sum, o);
    if ((t & 31) == 0) red[t >> 5] = sum;
    __syncthreads();
    float tot = 0.0f;
#pragma unroll
    for (int i = 0; i < 8; i++) tot += red[i];

    const float inv = __frcp_rn(tot);
#pragma unroll
    for (int i = 0; i < 8; i++)
        row[t + i * 256] = to_tf32(v[i] * inv);
}

// ---------------------------------------------------------------------------
extern "C" void kernel_launch(void* const* d_in, const int* in_sizes, int n_in,
                              void* d_out, int out_size)
{
    const float* q  = (const float*)d_in[0];
    const float* k  = (const float*)d_in[1];
    const float* v  = (const float*)d_in[2];
    const float* Wq = (const float*)d_in[3];
    const float* bq = (const float*)d_in[4];
    const float* Wk = (const float*)d_in[5];
    const float* bk = (const float*)d_in[6];
    const float* Wv = (const float*)d_in[7];
    const float* bv = (const float*)d_in[8];
    float* out = (float*)d_out;

    float *Qp, *Kp, *Vp, *Sc, *rq, *rk, *rv, *rWq, *rWk, *rWv;
    cudaGetSymbolAddress((void**)&Qp, g_Qp);
    cudaGetSymbolAddress((void**)&Kp, g_Kp);
    cudaGetSymbolAddress((void**)&Vp, g_Vp);
    cudaGetSymbolAddress((void**)&Sc, g_Sc);
    cudaGetSymbolAddress((void**)&rq, g_rq);
    cudaGetSymbolAddress((void**)&rk, g_rk);
    cudaGetSymbolAddress((void**)&rv, g_rv);
    cudaGetSymbolAddress((void**)&rWq, g_rWq);
    cudaGetSymbolAddress((void**)&rWk, g_rWk);
    cudaGetSymbolAddress((void**)&rWv, g_rWv);

    constexpr int SMEM_NN = SmemCfg<false>::SMEM_BYTES;   // 105984
    constexpr int SMEM_TN = SmemCfg<true >::SMEM_BYTES;   // 110592

    cudaFuncSetAttribute(mmagemm<false, true,  true >, cudaFuncAttributeMaxDynamicSharedMemorySize, SMEM_NN);
    cudaFuncSetAttribute(mmagemm<true,  false, false>, cudaFuncAttributeMaxDynamicSharedMemorySize, SMEM_TN);
    cudaFuncSetAttribute(mmagemm<false, false, false>, cudaFuncAttributeMaxDynamicSharedMemorySize, SMEM_NN);

    const long nQKV = (long)BB * SS * DD;
    const long nW   = (long)DD * DD;

    // 0) rna-round all GEMM operands to tf32
    round_tf32_kernel<<<2048, 256>>>(q,  rq,  nQKV / 4);
    round_tf32_kernel<<<2048, 256>>>(k,  rk,  nQKV / 4);
    round_tf32_kernel<<<2048, 256>>>(v,  rv,  nQKV / 4);
    round_tf32_kernel<<<512,  256>>>(Wq, rWq, nW / 4);
    round_tf32_kernel<<<512,  256>>>(Wk, rWk, nW / 4);
    round_tf32_kernel<<<512,  256>>>(Wv, rWv, nW / 4);

    const dim3 blk(256);

    // 1) Projections (NN + bias, round outputs): M=8192, N=1024, K=1024
    {
        dim3 g(DD / 128, (BB * SS) / 128, 1);
        mmagemm<false, true, true><<<g, blk, SMEM_NN>>>(rq, rWq, bq, Qp, BB * SS, DD, DD, 1.0f, 0, 0, 0);
        mmagemm<false, true, true><<<g, blk, SMEM_NN>>>(rk, rWk, bk, Kp, BB * SS, DD, DD, 1.0f, 0, 0, 0);
        mmagemm<false, true, true><<<g, blk, SMEM_NN>>>(rv, rWv, bv, Vp, BB * SS, DD, DD, 1.0f, 0, 0, 0);
    }

    // 2) Scores (TN): S = (1/32) Qp @ Kp^T per batch
    {
        dim3 g(SS / 128, SS / 128, BB);
        mmagemm<true, false, false><<<g, blk, SMEM_TN>>>(Qp, Kp, nullptr, Sc,
                                                         SS, SS, DD, 0.03125f,
                                                         (long)SS * DD, (long)SS * DD, (long)SS * SS);
    }

    // 3) Softmax (rounds to tf32)
    softmax2048<<<BB * SS, 256>>>(Sc);

    // 4) PV (NN): O = W @ Vp per batch: M=2048, N=1024, K=2048
    {
        dim3 g(DD / 128, SS / 128, BB);
        mmagemm<false, false, false><<<g, blk, SMEM_NN>>>(Sc, Vp, nullptr, out,
                                                          SS, DD, SS, 1.0f,
                                                          (long)SS * SS, (long)SS * DD, (long)SS * DD);
    }
}

// round 6
// speedup vs baseline: 5.0668x; 2.4549x over previous
#include <cuda_runtime.h>
#include <cuda_fp16.h>
#include <cstdint>
#include <math.h>

#define BB 4
#define SS 2048
#define DD 1024

// Scratch (__device__ globals — allocation-free rule). 16B-aligned for cp.async.
__device__ __align__(256) __half g_qh [(size_t)BB * SS * DD];
__device__ __align__(256) __half g_kh [(size_t)BB * SS * DD];
__device__ __align__(256) __half g_vh [(size_t)BB * SS * DD];
__device__ __align__(256) __half g_WqT[(size_t)DD * DD];
__device__ __align__(256) __half g_WkT[(size_t)DD * DD];
__device__ __align__(256) __half g_WvT[(size_t)DD * DD];
__device__ __align__(256) __half g_Qp [(size_t)BB * SS * DD];
__device__ __align__(256) __half g_Kp [(size_t)BB * SS * DD];
__device__ __align__(256) __half g_Vp [(size_t)BB * SS * DD];
__device__ __align__(256) __half g_VpT[(size_t)BB * SS * DD];
__device__ __align__(256) float  g_Sc [(size_t)BB * SS * SS];
__device__ __align__(256) __half g_Ph [(size_t)BB * SS * SS];

// ---------------------------------------------------------------------------
// PTX helpers
// ---------------------------------------------------------------------------
__device__ __forceinline__ void cp16(uint32_t dst, const void* src) {
    asm volatile("cp.async.cg.shared.global [%0], [%1], 16;" :: "r"(dst), "l"(src));
}
__device__ __forceinline__ void cp_commit() {
    asm volatile("cp.async.commit_group;");
}
__device__ __forceinline__ void ldsm4(uint32_t* r, uint32_t addr) {
    asm volatile("ldmatrix.sync.aligned.m8n8.x4.shared.b16 {%0,%1,%2,%3}, [%4];"
        : "=r"(r[0]), "=r"(r[1]), "=r"(r[2]), "=r"(r[3]) : "r"(addr));
}
__device__ __forceinline__ void mma_f16(float* c, const uint32_t* a, const uint32_t* b) {
    asm volatile(
        "mma.sync.aligned.m16n8k16.row.col.f32.f16.f16.f32 "
        "{%0,%1,%2,%3}, {%4,%5,%6,%7}, {%8,%9}, {%0,%1,%2,%3};"
        : "+f"(c[0]), "+f"(c[1]), "+f"(c[2]), "+f"(c[3])
        : "r"(a[0]), "r"(a[1]), "r"(a[2]), "r"(a[3]), "r"(b[0]), "r"(b[1]));
}

// ---------------------------------------------------------------------------
// FP16 TN tensor-core GEMM: C[m,n] = alpha * sum_k A[m,k]*B[n,k] (+ bias[n])
//   A: [M,K] half row-major, B: [N,K] half row-major (both K-major).
//   256 threads, tile 128x128x32, 8 warps (2m x 4n, warp tile 64x32),
//   3-stage cp.async pipeline, ldmatrix fragment loads.
// ---------------------------------------------------------------------------
#define STAGES 3
#define AST 40                              // smem row stride in halves (80 B)
#define TILE_HALVES (128 * AST)             // 5120
#define STAGE_BYTES (2 * TILE_HALVES * 2)   // 20480
#define GEMM_SMEM (STAGES * STAGE_BYTES)    // 61440

template <bool HAS_BIAS, bool OUT_HALF>
__global__ __launch_bounds__(256, 2)
void hgemm_tn(const __half* __restrict__ A, const __half* __restrict__ B,
              const float* __restrict__ bias, void* __restrict__ Cv,
              int N, int K, float alpha, long sAz, long sBz, long sCz)
{
    extern __shared__ __half sm[];
    const int tid  = threadIdx.x;
    const int lane = tid & 31;
    const int warp = tid >> 5;
    const int m0 = blockIdx.y * 128;
    const int n0 = blockIdx.x * 128;

    const __half* Ab = A + (long)blockIdx.z * sAz;
    const __half* Bb = B + (long)blockIdx.z * sBz;

    const int wm = (warp >> 2) * 64;
    const int wn = (warp & 3) * 32;
    const int r  = lane >> 2;
    const int cc = lane & 3;

    const uint32_t smBase = (uint32_t)__cvta_generic_to_shared(sm);

    // ldmatrix per-lane offsets (in halves)
    // A/B (x4, 16x16): lanes 0-15 -> rows 0..15 at k+0; lanes 16-31 -> rows 0..15 at k+8
    const int aLane = (lane & 15) * AST + (lane >> 4) * 8;
    // B (x4 over n16): lanes 0-7: n0-7,k0; 8-15: n0-7,k8; 16-23: n8-15,k0; 24-31: n8-15,k8
    const int bLane = (((lane >> 4) << 3) + (lane & 7)) * AST + ((lane >> 3) & 1) * 8;

    auto load_tiles = [&](int stage, int k0) {
        const uint32_t aS = smBase + (uint32_t)stage * STAGE_BYTES;
        const uint32_t bS = aS + TILE_HALVES * 2;
#pragma unroll
        for (int i = 0; i < 2; i++) {
            const int c   = tid + 256 * i;     // 512 chunks of 8 halves
            const int row = c >> 2;
            const int c16 = (c & 3) * 8;
            cp16(aS + (uint32_t)(row * AST + c16) * 2, Ab + (long)(m0 + row) * K + k0 + c16);
            cp16(bS + (uint32_t)(row * AST + c16) * 2, Bb + (long)(n0 + row) * K + k0 + c16);
        }
    };

    float acc[4][4][4];
#pragma unroll
    for (int mt = 0; mt < 4; mt++)
#pragma unroll
        for (int nt = 0; nt < 4; nt++)
#pragma unroll
            for (int i = 0; i < 4; i++) acc[mt][nt][i] = 0.0f;

    const int KT = K / 32;
#pragma unroll
    for (int s = 0; s < STAGES; s++) {
        if (s < KT) { load_tiles(s, s * 32); cp_commit(); }
    }

    for (int t = 0; t < KT; t++) {
        const int rem = KT - 1 - t;
        if (rem >= 2)      asm volatile("cp.async.wait_group 2;");
        else if (rem == 1) asm volatile("cp.async.wait_group 1;");
        else               asm volatile("cp.async.wait_group 0;");
        __syncthreads();

        const int stage = t % STAGES;
        const uint32_t aS = smBase + (uint32_t)stage * STAGE_BYTES;
        const uint32_t bS = aS + TILE_HALVES * 2;

#pragma unroll
        for (int k16 = 0; k16 < 32; k16 += 16) {
            uint32_t afr[4][4], bfr[2][4];
#pragma unroll
            for (int mt = 0; mt < 4; mt++)
                ldsm4(afr[mt], aS + (uint32_t)((wm + mt * 16) * AST + k16 + aLane) * 2);
#pragma unroll
            for (int ng = 0; ng < 2; ng++)
                ldsm4(bfr[ng], bS + (uint32_t)((wn + ng * 16) * AST + k16 + bLane) * 2);
#pragma unroll
            for (int mt = 0; mt < 4; mt++)
#pragma unroll
                for (int nt = 0; nt < 4; nt++)
                    mma_f16(acc[mt][nt], afr[mt], &bfr[nt >> 1][(nt & 1) * 2]);
        }
        __syncthreads();

        if (t + STAGES < KT) { load_tiles(stage, (t + STAGES) * 32); cp_commit(); }
    }

    // epilogue
#pragma unroll
    for (int mt = 0; mt < 4; mt++) {
        const long row0 = m0 + wm + mt * 16 + r;
#pragma unroll
        for (int nt = 0; nt < 4; nt++) {
            const int colb = n0 + wn + nt * 8 + 2 * cc;
            float x0 = acc[mt][nt][0] * alpha;
            float x1 = acc[mt][nt][1] * alpha;
            float x2 = acc[mt][nt][2] * alpha;
            float x3 = acc[mt][nt][3] * alpha;
            if (HAS_BIAS) {
                const float b0 = bias[colb], b1 = bias[colb + 1];
                x0 += b0; x1 += b1; x2 += b0; x3 += b1;
            }
            if (OUT_HALF) {
                __half* Cb = (__half*)Cv + (long)blockIdx.z * sCz;
                *(__half2*)(Cb + row0 * N + colb)       = __floats2half2_rn(x0, x1);
                *(__half2*)(Cb + (row0 + 8) * N + colb) = __floats2half2_rn(x2, x3);
            } else {
                float* Cb = (float*)Cv + (long)blockIdx.z * sCz;
                *(float2*)(Cb + row0 * N + colb)       = make_float2(x0, x1);
                *(float2*)(Cb + (row0 + 8) * N + colb) = make_float2(x2, x3);
            }
        }
    }
}

// ---------------------------------------------------------------------------
// Elementwise fp32 -> fp16(rn)
// ---------------------------------------------------------------------------
__global__ __launch_bounds__(256)
void f2h_kernel(const float* __restrict__ in, __half* __restrict__ out, long n4)
{
    long i = (long)blockIdx.x * blockDim.x + threadIdx.x;
    const long stride = (long)gridDim.x * blockDim.x;
    for (; i < n4; i += stride) {
        float4 v = ((const float4*)in)[i];
        __half2* o = (__half2*)(out + i * 4);
        o[0] = __floats2half2_rn(v.x, v.y);
        o[1] = __floats2half2_rn(v.z, v.w);
    }
}

// ---------------------------------------------------------------------------
// Transpose + convert: W f32 [K][N] -> half [N][K]  (1024x1024)
// ---------------------------------------------------------------------------
__global__ __launch_bounds__(256)
void wtrans_kernel(const float* __restrict__ in, __half* __restrict__ out)
{
    __shared__ float t[32][33];
    const int bx = blockIdx.x * 32;   // n
    const int by = blockIdx.y * 32;   // k
    const int tx = threadIdx.x, ty = threadIdx.y;
#pragma unroll
    for (int i = ty; i < 32; i += 8)
        t[i][tx] = in[(long)(by + i) * DD + bx + tx];
    __syncthreads();
#pragma unroll
    for (int i = ty; i < 32; i += 8)
        out[(long)(bx + i) * DD + by + tx] = __float2half_rn(t[tx][i]);
}

// ---------------------------------------------------------------------------
// Half transpose (batched): in [rows][cols] -> out [cols][rows]
// ---------------------------------------------------------------------------
__global__ __launch_bounds__(256)
void htrans_kernel(const __half* __restrict__ in, __half* __restrict__ out,
                   int rows, int cols)
{
    __shared__ __half t[32][34];
    const int bx = blockIdx.x * 32;   // col
    const int by = blockIdx.y * 32;   // row
    const int tx = threadIdx.x, ty = threadIdx.y;
    const __half* ib = in  + (long)blockIdx.z * rows * cols;
    __half*       ob = out + (long)blockIdx.z * rows * cols;
#pragma unroll
    for (int i = ty; i < 32; i += 8)
        t[i][tx] = ib[(long)(by + i) * cols + bx + tx];
    __syncthreads();
#pragma unroll
    for (int i = ty; i < 32; i += 8)
        ob[(long)(bx + i) * rows + by + tx] = t[tx][i];
}

// ---------------------------------------------------------------------------
// Row softmax over 2048 fp32 cols -> fp16 probabilities
// ---------------------------------------------------------------------------
__global__ __launch_bounds__(256)
void softmax2048_h(const float* __restrict__ S, __half* __restrict__ P)
{
    const float* row = S + (long)blockIdx.x * SS;
    __half*      po  = P + (long)blockIdx.x * SS;
    const int t = threadIdx.x;

    float v[8];
    float mx = -1e30f;
#pragma unroll
    for (int i = 0; i < 8; i++) {
        v[i] = row[t + i * 256];
        mx = fmaxf(mx, v[i]);
    }
#pragma unroll
    for (int o = 16; o > 0; o >>= 1)
        mx = fmaxf(mx, __shfl_xor_sync(0xFFFFFFFFu, mx, o));

    __shared__ float red[8];
    if ((t & 31) == 0) red[t >> 5] = mx;
    __syncthreads();
    float bmax = red[0];
#pragma unroll
    for (int i = 1; i < 8; i++) bmax = fmaxf(bmax, red[i]);
    __syncthreads();

    float sum = 0.0f;
#pragma unroll
    for (int i = 0; i < 8; i++) {
        v[i] = __expf(v[i] - bmax);
        sum += v[i];
    }
#pragma unroll
    for (int o = 16; o > 0; o >>= 1)
        sum += __shfl_xor_sync(0xFFFFFFFFu, sum, o);
    if ((t & 31) == 0) red[t >> 5] = sum;
    __syncthreads();
    float tot = 0.0f;
#pragma unroll
    for (int i = 0; i < 8; i++) tot += red[i];

    const float inv = __frcp_rn(tot);
#pragma unroll
    for (int i = 0; i < 8; i++)
        po[t + i * 256] = __float2half_rn(v[i] * inv);
}

// ---------------------------------------------------------------------------
extern "C" void kernel_launch(void* const* d_in, const int* in_sizes, int n_in,
                              void* d_out, int out_size)
{
    const float* q  = (const float*)d_in[0];
    const float* k  = (const float*)d_in[1];
    const float* v  = (const float*)d_in[2];
    const float* Wq = (const float*)d_in[3];
    const float* bq = (const float*)d_in[4];
    const float* Wk = (const float*)d_in[5];
    const float* bk = (const float*)d_in[6];
    const float* Wv = (const float*)d_in[7];
    const float* bv = (const float*)d_in[8];
    float* out = (float*)d_out;

    __half *qh, *kh, *vh, *WqT, *WkT, *WvT, *Qp, *Kp, *Vp, *VpT, *Ph;
    float *Sc;
    cudaGetSymbolAddress((void**)&qh,  g_qh);
    cudaGetSymbolAddress((void**)&kh,  g_kh);
    cudaGetSymbolAddress((void**)&vh,  g_vh);
    cudaGetSymbolAddress((void**)&WqT, g_WqT);
    cudaGetSymbolAddress((void**)&WkT, g_WkT);
    cudaGetSymbolAddress((void**)&WvT, g_WvT);
    cudaGetSymbolAddress((void**)&Qp,  g_Qp);
    cudaGetSymbolAddress((void**)&Kp,  g_Kp);
    cudaGetSymbolAddress((void**)&Vp,  g_Vp);
    cudaGetSymbolAddress((void**)&VpT, g_VpT);
    cudaGetSymbolAddress((void**)&Sc,  g_Sc);
    cudaGetSymbolAddress((void**)&Ph,  g_Ph);

    cudaFuncSetAttribute(hgemm_tn<true,  true >, cudaFuncAttributeMaxDynamicSharedMemorySize, GEMM_SMEM);
    cudaFuncSetAttribute(hgemm_tn<false, false>, cudaFuncAttributeMaxDynamicSharedMemorySize, GEMM_SMEM);

    const long nQKV = (long)BB * SS * DD;

    // 0) convert inputs to fp16; transpose+convert weights
    f2h_kernel<<<2048, 256>>>(q, qh, nQKV / 4);
    f2h_kernel<<<2048, 256>>>(k, kh, nQKV / 4);
    f2h_kernel<<<2048, 256>>>(v, vh, nQKV / 4);
    {
        dim3 g(32, 32), b(32, 8);
        wtrans_kernel<<<g, b>>>(Wq, WqT);
        wtrans_kernel<<<g, b>>>(Wk, WkT);
        wtrans_kernel<<<g, b>>>(Wv, WvT);
    }

    const dim3 blk(256);

    // 1) Projections (TN, bias, half out): M=8192, N=1024, K=1024
    {
        dim3 g(DD / 128, (BB * SS) / 128, 1);
        hgemm_tn<true, true><<<g, blk, GEMM_SMEM>>>(qh, WqT, bq, Qp, DD, DD, 1.0f, 0, 0, 0);
        hgemm_tn<true, true><<<g, blk, GEMM_SMEM>>>(kh, WkT, bk, Kp, DD, DD, 1.0f, 0, 0, 0);
        hgemm_tn<true, true><<<g, blk, GEMM_SMEM>>>(vh, WvT, bv, Vp, DD, DD, 1.0f, 0, 0, 0);
    }

    // 1b) transpose Vp per batch: [S][D] -> [D][S]
    {
        dim3 g(DD / 32, SS / 32, BB), b(32, 8);
        htrans_kernel<<<g, b>>>(Vp, VpT, SS, DD);
    }

    // 2) Scores (TN, f32 out): per batch M=N=2048, K=1024, alpha=1/32
    {
        dim3 g(SS / 128, SS / 128, BB);
        hgemm_tn<false, false><<<g, blk, GEMM_SMEM>>>(Qp, Kp, nullptr, Sc,
                                                      SS, DD, 0.03125f,
                                                      (long)SS * DD, (long)SS * DD, (long)SS * SS);
    }

    // 3) Softmax (f32 -> f16 probs)
    softmax2048_h<<<BB * SS, 256>>>(Sc, Ph);

    // 4) PV (TN, f32 out): A=Ph [S,S], B=VpT [D][S]; M=2048, N=1024, K=2048
    {
        dim3 g(DD / 128, SS / 128, BB);
        hgemm_tn<false, false><<<g, blk, GEMM_SMEM>>>(Ph, VpT, nullptr, out,
                                                      DD, SS, 1.0f,
                                                      (long)SS * SS, (long)SS * DD, (long)SS * DD);
    }
}

// round 7
// speedup vs baseline: 5.1078x; 1.0081x over previous
#include <cuda_runtime.h>
#include <cuda_fp16.h>
#include <cstdint>
#include <math.h>

#define BB 4
#define SS 2048
#define DD 1024

// Scratch (__device__ globals — allocation-free rule). 16B-aligned for cp.async.
__device__ __align__(256) __half g_qh [(size_t)BB * SS * DD];
__device__ __align__(256) __half g_kh [(size_t)BB * SS * DD];
__device__ __align__(256) __half g_vh [(size_t)BB * SS * DD];
__device__ __align__(256) __half g_WqT[(size_t)DD * DD];
__device__ __align__(256) __half g_WkT[(size_t)DD * DD];
__device__ __align__(256) __half g_WvT[(size_t)DD * DD];
__device__ __align__(256) __half g_Qp [(size_t)BB * SS * DD];
__device__ __align__(256) __half g_Kp [(size_t)BB * SS * DD];
__device__ __align__(256) __half g_Vp [(size_t)BB * SS * DD];
__device__ __align__(256) __half g_VpT[(size_t)BB * SS * DD];
__device__ __align__(256) float  g_Sc [(size_t)BB * SS * SS];
__device__ __align__(256) __half g_Ph [(size_t)BB * SS * SS];

// ---------------------------------------------------------------------------
// PTX helpers
// ---------------------------------------------------------------------------
__device__ __forceinline__ void cp16(uint32_t dst, const void* src) {
    asm volatile("cp.async.cg.shared.global [%0], [%1], 16;" :: "r"(dst), "l"(src));
}
__device__ __forceinline__ void cp_commit() {
    asm volatile("cp.async.commit_group;");
}
__device__ __forceinline__ void ldsm4(uint32_t* r, uint32_t addr) {
    asm volatile("ldmatrix.sync.aligned.m8n8.x4.shared.b16 {%0,%1,%2,%3}, [%4];"
        : "=r"(r[0]), "=r"(r[1]), "=r"(r[2]), "=r"(r[3]) : "r"(addr));
}
__device__ __forceinline__ void mma_f16(float* c, const uint32_t* a, const uint32_t* b) {
    asm volatile(
        "mma.sync.aligned.m16n8k16.row.col.f32.f16.f16.f32 "
        "{%0,%1,%2,%3}, {%4,%5,%6,%7}, {%8,%9}, {%0,%1,%2,%3};"
        : "+f"(c[0]), "+f"(c[1]), "+f"(c[2]), "+f"(c[3])
        : "r"(a[0]), "r"(a[1]), "r"(a[2]), "r"(a[3]), "r"(b[0]), "r"(b[1]));
}

// ---------------------------------------------------------------------------
// FP16 TN tensor-core GEMM: C[m,n] = alpha * sum_k A[m,k]*B[n,k] (+ bias[n])
//   A: [M,K] half row-major, B: [N,K] half row-major (both K-major).
//   128 threads, CTA tile 128x128x32, 4 warps (2m x 2n, warp tile 64x64),
//   3-stage cp.async pipeline, ldmatrix fragment loads.
// ---------------------------------------------------------------------------
#define STAGES 3
#define AST 40                              // smem row stride in halves (80 B)
#define TILE_HALVES (128 * AST)             // 5120
#define STAGE_BYTES (2 * TILE_HALVES * 2)   // 20480
#define GEMM_SMEM (STAGES * STAGE_BYTES)    // 61440

template <bool HAS_BIAS, bool OUT_HALF>
__global__ __launch_bounds__(128, 2)
void hgemm_tn(const __half* __restrict__ A, const __half* __restrict__ B,
              const float* __restrict__ bias, void* __restrict__ Cv,
              int N, int K, float alpha, long sAz, long sBz, long sCz)
{
    extern __shared__ __half sm[];
    const int tid  = threadIdx.x;
    const int lane = tid & 31;
    const int warp = tid >> 5;
    const int m0 = blockIdx.y * 128;
    const int n0 = blockIdx.x * 128;

    const __half* Ab = A + (long)blockIdx.z * sAz;
    const __half* Bb = B + (long)blockIdx.z * sBz;

    // 4 warps: 2(m) x 2(n); warp tile 64x64
    const int wm = (warp >> 1) * 64;
    const int wn = (warp & 1) * 64;
    const int r  = lane >> 2;
    const int cc = lane & 3;

    const uint32_t smBase = (uint32_t)__cvta_generic_to_shared(sm);

    // ldmatrix per-lane offsets (in halves)
    const int aLane = (lane & 15) * AST + (lane >> 4) * 8;
    const int bLane = (((lane >> 4) << 3) + (lane & 7)) * AST + ((lane >> 3) & 1) * 8;

    auto load_tiles = [&](int stage, int k0) {
        const uint32_t aS = smBase + (uint32_t)stage * STAGE_BYTES;
        const uint32_t bS = aS + TILE_HALVES * 2;
#pragma unroll
        for (int i = 0; i < 4; i++) {
            const int c   = tid + 128 * i;     // 512 chunks of 8 halves per tile
            const int row = c >> 2;
            const int c16 = (c & 3) * 8;
            cp16(aS + (uint32_t)(row * AST + c16) * 2, Ab + (long)(m0 + row) * K + k0 + c16);
            cp16(bS + (uint32_t)(row * AST + c16) * 2, Bb + (long)(n0 + row) * K + k0 + c16);
        }
    };

    float acc[4][8][4];
#pragma unroll
    for (int mt = 0; mt < 4; mt++)
#pragma unroll
        for (int nt = 0; nt < 8; nt++)
#pragma unroll
            for (int i = 0; i < 4; i++) acc[mt][nt][i] = 0.0f;

    const int KT = K / 32;
#pragma unroll
    for (int s = 0; s < STAGES; s++) {
        if (s < KT) { load_tiles(s, s * 32); cp_commit(); }
    }

    for (int t = 0; t < KT; t++) {
        const int rem = KT - 1 - t;
        if (rem >= 2)      asm volatile("cp.async.wait_group 2;");
        else if (rem == 1) asm volatile("cp.async.wait_group 1;");
        else               asm volatile("cp.async.wait_group 0;");
        __syncthreads();

        const int stage = t % STAGES;
        const uint32_t aS = smBase + (uint32_t)stage * STAGE_BYTES;
        const uint32_t bS = aS + TILE_HALVES * 2;

#pragma unroll
        for (int k16 = 0; k16 < 32; k16 += 16) {
            uint32_t afr[4][4], bfr[4][4];
#pragma unroll
            for (int mt = 0; mt < 4; mt++)
                ldsm4(afr[mt], aS + (uint32_t)((wm + mt * 16) * AST + k16 + aLane) * 2);
#pragma unroll
            for (int ng = 0; ng < 4; ng++)
                ldsm4(bfr[ng], bS + (uint32_t)((wn + ng * 16) * AST + k16 + bLane) * 2);
#pragma unroll
            for (int mt = 0; mt < 4; mt++)
#pragma unroll
                for (int nt = 0; nt < 8; nt++)
                    mma_f16(acc[mt][nt], afr[mt], &bfr[nt >> 1][(nt & 1) * 2]);
        }
        __syncthreads();

        if (t + STAGES < KT) { load_tiles(stage, (t + STAGES) * 32); cp_commit(); }
    }

    // epilogue
#pragma unroll
    for (int mt = 0; mt < 4; mt++) {
        const long row0 = m0 + wm + mt * 16 + r;
#pragma unroll
        for (int nt = 0; nt < 8; nt++) {
            const int colb = n0 + wn + nt * 8 + 2 * cc;
            float x0 = acc[mt][nt][0] * alpha;
            float x1 = acc[mt][nt][1] * alpha;
            float x2 = acc[mt][nt][2] * alpha;
            float x3 = acc[mt][nt][3] * alpha;
            if (HAS_BIAS) {
                const float b0 = bias[colb], b1 = bias[colb + 1];
                x0 += b0; x1 += b1; x2 += b0; x3 += b1;
            }
            if (OUT_HALF) {
                __half* Cb = (__half*)Cv + (long)blockIdx.z * sCz;
                *(__half2*)(Cb + row0 * N + colb)       = __floats2half2_rn(x0, x1);
                *(__half2*)(Cb + (row0 + 8) * N + colb) = __floats2half2_rn(x2, x3);
            } else {
                float* Cb = (float*)Cv + (long)blockIdx.z * sCz;
                *(float2*)(Cb + row0 * N + colb)       = make_float2(x0, x1);
                *(float2*)(Cb + (row0 + 8) * N + colb) = make_float2(x2, x3);
            }
        }
    }
}

// ---------------------------------------------------------------------------
// Batched fp32 -> fp16(rn): z selects which of 3 arrays
// ---------------------------------------------------------------------------
__global__ __launch_bounds__(256)
void f2h3_kernel(const float* __restrict__ a0, const float* __restrict__ a1,
                 const float* __restrict__ a2, __half* __restrict__ o0,
                 __half* __restrict__ o1, __half* __restrict__ o2, long n4)
{
    const float* in = (blockIdx.z == 0) ? a0 : (blockIdx.z == 1) ? a1 : a2;
    __half* out     = (blockIdx.z == 0) ? o0 : (blockIdx.z == 1) ? o1 : o2;
    long i = (long)blockIdx.x * blockDim.x + threadIdx.x;
    const long stride = (long)gridDim.x * blockDim.x;
    for (; i < n4; i += stride) {
        float4 v = ((const float4*)in)[i];
        __half2* o = (__half2*)(out + i * 4);
        o[0] = __floats2half2_rn(v.x, v.y);
        o[1] = __floats2half2_rn(v.z, v.w);
    }
}

// ---------------------------------------------------------------------------
// Batched transpose + convert: W f32 [K][N] -> half [N][K] (z selects weight)
// ---------------------------------------------------------------------------
__global__ __launch_bounds__(256)
void wtrans3_kernel(const float* __restrict__ a0, const float* __restrict__ a1,
                    const float* __restrict__ a2, __half* __restrict__ o0,
                    __half* __restrict__ o1, __half* __restrict__ o2)
{
    const float* in = (blockIdx.z == 0) ? a0 : (blockIdx.z == 1) ? a1 : a2;
    __half* out     = (blockIdx.z == 0) ? o0 : (blockIdx.z == 1) ? o1 : o2;
    __shared__ float t[32][33];
    const int bx = blockIdx.x * 32;   // n
    const int by = blockIdx.y * 32;   // k
    const int tx = threadIdx.x, ty = threadIdx.y;
#pragma unroll
    for (int i = ty; i < 32; i += 8)
        t[i][tx] = in[(long)(by + i) * DD + bx + tx];
    __syncthreads();
#pragma unroll
    for (int i = ty; i < 32; i += 8)
        out[(long)(bx + i) * DD + by + tx] = __float2half_rn(t[tx][i]);
}

// ---------------------------------------------------------------------------
// Half transpose (batched): in [rows][cols] -> out [cols][rows]
// ---------------------------------------------------------------------------
__global__ __launch_bounds__(256)
void htrans_kernel(const __half* __restrict__ in, __half* __restrict__ out,
                   int rows, int cols)
{
    __shared__ __half t[32][34];
    const int bx = blockIdx.x * 32;   // col
    const int by = blockIdx.y * 32;   // row
    const int tx = threadIdx.x, ty = threadIdx.y;
    const __half* ib = in  + (long)blockIdx.z * rows * cols;
    __half*       ob = out + (long)blockIdx.z * rows * cols;
#pragma unroll
    for (int i = ty; i < 32; i += 8)
        t[i][tx] = ib[(long)(by + i) * cols + bx + tx];
    __syncthreads();
#pragma unroll
    for (int i = ty; i < 32; i += 8)
        ob[(long)(bx + i) * rows + by + tx] = t[tx][i];
}

// ---------------------------------------------------------------------------
// Row softmax over 2048 fp32 cols -> fp16 probabilities
// ---------------------------------------------------------------------------
__global__ __launch_bounds__(256)
void softmax2048_h(const float* __restrict__ S, __half* __restrict__ P)
{
    const float* row = S + (long)blockIdx.x * SS;
    __half*      po  = P + (long)blockIdx.x * SS;
    const int t = threadIdx.x;

    float v[8];
    float mx = -1e30f;
#pragma unroll
    for (int i = 0; i < 8; i++) {
        v[i] = row[t + i * 256];
        mx = fmaxf(mx, v[i]);
    }
#pragma unroll
    for (int o = 16; o > 0; o >>= 1)
        mx = fmaxf(mx, __shfl_xor_sync(0xFFFFFFFFu, mx, o));

    __shared__ float red[8];
    if ((t & 31) == 0) red[t >> 5] = mx;
    __syncthreads();
    float bmax = red[0];
#pragma unroll
    for (int i = 1; i < 8; i++) bmax = fmaxf(bmax, red[i]);
    __syncthreads();

    float sum = 0.0f;
#pragma unroll
    for (int i = 0; i < 8; i++) {
        v[i] = __expf(v[i] - bmax);
        sum += v[i];
    }
#pragma unroll
    for (int o = 16; o > 0; o >>= 1)
        sum += __shfl_xor_sync(0xFFFFFFFFu, sum, o);
    if ((t & 31) == 0) red[t >> 5] = sum;
    __syncthreads();
    float tot = 0.0f;
#pragma unroll
    for (int i = 0; i < 8; i++) tot += red[i];

    const float inv = __frcp_rn(tot);
#pragma unroll
    for (int i = 0; i < 8; i++)
        po[t + i * 256] = __float2half_rn(v[i] * inv);
}

// ---------------------------------------------------------------------------
extern "C" void kernel_launch(void* const* d_in, const int* in_sizes, int n_in,
                              void* d_out, int out_size)
{
    const float* q  = (const float*)d_in[0];
    const float* k  = (const float*)d_in[1];
    const float* v  = (const float*)d_in[2];
    const float* Wq = (const float*)d_in[3];
    const float* bq = (const float*)d_in[4];
    const float* Wk = (const float*)d_in[5];
    const float* bk = (const float*)d_in[6];
    const float* Wv = (const float*)d_in[7];
    const float* bv = (const float*)d_in[8];
    float* out = (float*)d_out;

    __half *qh, *kh, *vh, *WqT, *WkT, *WvT, *Qp, *Kp, *Vp, *VpT, *Ph;
    float *Sc;
    cudaGetSymbolAddress((void**)&qh,  g_qh);
    cudaGetSymbolAddress((void**)&kh,  g_kh);
    cudaGetSymbolAddress((void**)&vh,  g_vh);
    cudaGetSymbolAddress((void**)&WqT, g_WqT);
    cudaGetSymbolAddress((void**)&WkT, g_WkT);
    cudaGetSymbolAddress((void**)&WvT, g_WvT);
    cudaGetSymbolAddress((void**)&Qp,  g_Qp);
    cudaGetSymbolAddress((void**)&Kp,  g_Kp);
    cudaGetSymbolAddress((void**)&Vp,  g_Vp);
    cudaGetSymbolAddress((void**)&VpT, g_VpT);
    cudaGetSymbolAddress((void**)&Sc,  g_Sc);
    cudaGetSymbolAddress((void**)&Ph,  g_Ph);

    cudaFuncSetAttribute(hgemm_tn<true,  true >, cudaFuncAttributeMaxDynamicSharedMemorySize, GEMM_SMEM);
    cudaFuncSetAttribute(hgemm_tn<false, false>, cudaFuncAttributeMaxDynamicSharedMemorySize, GEMM_SMEM);

    const long nQKV = (long)BB * SS * DD;

    // 1: convert q/k/v to fp16 (one launch, grid.z = 3)
    {
        dim3 g(1024, 1, 3);
        f2h3_kernel<<<g, 256>>>(q, k, v, qh, kh, vh, nQKV / 4);
    }
    // 2: transpose+convert weights (one launch, grid.z = 3)
    {
        dim3 g(32, 32, 3), b(32, 8);
        wtrans3_kernel<<<g, b>>>(Wq, Wk, Wv, WqT, WkT, WvT);
    }

    const dim3 blk(128);

    // 3-5: Projections (TN, bias, half out): M=8192, N=1024, K=1024
    {
        dim3 g(DD / 128, (BB * SS) / 128, 1);
        hgemm_tn<true, true><<<g, blk, GEMM_SMEM>>>(qh, WqT, bq, Qp, DD, DD, 1.0f, 0, 0, 0);
        hgemm_tn<true, true><<<g, blk, GEMM_SMEM>>>(kh, WkT, bk, Kp, DD, DD, 1.0f, 0, 0, 0);
        hgemm_tn<true, true><<<g, blk, GEMM_SMEM>>>(vh, WvT, bv, Vp, DD, DD, 1.0f, 0, 0, 0);
    }

    // 6: Scores (TN, f32 out): per batch M=N=2048, K=1024, alpha=1/32
    //    (6th launch — ncu -s 5 -c 1 profiles this one)
    {
        dim3 g(SS / 128, SS / 128, BB);
        hgemm_tn<false, false><<<g, blk, GEMM_SMEM>>>(Qp, Kp, nullptr, Sc,
                                                      SS, DD, 0.03125f,
                                                      (long)SS * DD, (long)SS * DD, (long)SS * SS);
    }

    // 7: Softmax (f32 -> f16 probs)
    softmax2048_h<<<BB * SS, 256>>>(Sc, Ph);

    // 8: transpose Vp per batch: [S][D] -> [D][S]  (needed only by PV)
    {
        dim3 g(DD / 32, SS / 32, BB), b(32, 8);
        htrans_kernel<<<g, b>>>(Vp, VpT, SS, DD);
    }

    // 9: PV (TN, f32 out): A=Ph [S,S], B=VpT [D][S]; M=2048, N=1024, K=2048
    {
        dim3 g(DD / 128, SS / 128, BB);
        hgemm_tn<false, false><<<g, blk, GEMM_SMEM>>>(Ph, VpT, nullptr, out,
                                                      DD, SS, 1.0f,
                                                      (long)SS * SS, (long)SS * DD, (long)SS * DD);
    }
}

// round 8
// speedup vs baseline: 5.6876x; 1.1135x over previous
#include <cuda_runtime.h>
#include <cuda_fp16.h>
#include <cstdint>
#include <math.h>

#define BB 4
#define SS 2048
#define DD 1024

// Scratch (__device__ globals — allocation-free rule). 16B-aligned for cp.async.
__device__ __align__(256) __half g_qh [(size_t)BB * SS * DD];
__device__ __align__(256) __half g_kh [(size_t)BB * SS * DD];
__device__ __align__(256) __half g_vh [(size_t)BB * SS * DD];
__device__ __align__(256) __half g_WqT[(size_t)DD * DD];
__device__ __align__(256) __half g_WkT[(size_t)DD * DD];
__device__ __align__(256) __half g_WvT[(size_t)DD * DD];
__device__ __align__(256) __half g_Qp [(size_t)BB * SS * DD];
__device__ __align__(256) __half g_Kp [(size_t)BB * SS * DD];
__device__ __align__(256) __half g_Vp [(size_t)BB * SS * DD];
__device__ __align__(256) __half g_VpT[(size_t)BB * SS * DD];
__device__ __align__(256) float  g_Sc [(size_t)BB * SS * SS];
__device__ __align__(256) __half g_Ph [(size_t)BB * SS * SS];

// ---------------------------------------------------------------------------
// PTX helpers
// ---------------------------------------------------------------------------
__device__ __forceinline__ void cp16(uint32_t dst, const void* src) {
    asm volatile("cp.async.cg.shared.global [%0], [%1], 16;" :: "r"(dst), "l"(src));
}
__device__ __forceinline__ void cp_commit() {
    asm volatile("cp.async.commit_group;");
}
__device__ __forceinline__ void ldsm4(uint32_t* r, uint32_t addr) {
    asm volatile("ldmatrix.sync.aligned.m8n8.x4.shared.b16 {%0,%1,%2,%3}, [%4];"
        : "=r"(r[0]), "=r"(r[1]), "=r"(r[2]), "=r"(r[3]) : "r"(addr));
}
__device__ __forceinline__ void mma_f16(float* c, const uint32_t* a, const uint32_t* b) {
    asm volatile(
        "mma.sync.aligned.m16n8k16.row.col.f32.f16.f16.f32 "
        "{%0,%1,%2,%3}, {%4,%5,%6,%7}, {%8,%9}, {%0,%1,%2,%3};"
        : "+f"(c[0]), "+f"(c[1]), "+f"(c[2]), "+f"(c[3])
        : "r"(a[0]), "r"(a[1]), "r"(a[2]), "r"(a[3]), "r"(b[0]), "r"(b[1]));
}

// ---------------------------------------------------------------------------
// FP16 TN tensor-core GEMM: C[m,n] = alpha * sum_k A[m,k]*B[n,k] (+ bias[n])
//   A: [M,K] half row-major, B: [N,K] half row-major (both K-major).
//   128 threads, CTA tile 128x128x64, 4 warps (2m x 2n, warp tile 64x64),
//   3-stage cp.async pipeline, fragment double-buffering across k16 steps.
// ---------------------------------------------------------------------------
#define STAGES 3
#define BK 64
#define AST 72                              // smem row stride in halves (144 B)
#define TILE_HALVES (128 * AST)             // 9216
#define STAGE_BYTES (2 * TILE_HALVES * 2)   // 36864
#define GEMM_SMEM (STAGES * STAGE_BYTES)    // 110592

template <bool HAS_BIAS, bool OUT_HALF>
__global__ __launch_bounds__(128)
void hgemm_tn(const __half* __restrict__ A, const __half* __restrict__ B,
              const float* __restrict__ bias, void* __restrict__ Cv,
              int N, int K, float alpha, long sAz, long sBz, long sCz)
{
    extern __shared__ __half sm[];
    const int tid  = threadIdx.x;
    const int lane = tid & 31;
    const int warp = tid >> 5;
    const int m0 = blockIdx.y * 128;
    const int n0 = blockIdx.x * 128;

    const __half* Ab = A + (long)blockIdx.z * sAz;
    const __half* Bb = B + (long)blockIdx.z * sBz;

    // 4 warps: 2(m) x 2(n); warp tile 64x64
    const int wm = (warp >> 1) * 64;
    const int wn = (warp & 1) * 64;
    const int r  = lane >> 2;
    const int cc = lane & 3;

    const uint32_t smBase = (uint32_t)__cvta_generic_to_shared(sm);

    // ldmatrix per-lane offsets (in halves)
    const int aLane = (lane & 15) * AST + (lane >> 4) * 8;
    const int bLane = (((lane >> 4) << 3) + (lane & 7)) * AST + ((lane >> 3) & 1) * 8;

    auto load_tiles = [&](int stage, int k0) {
        const uint32_t aS = smBase + (uint32_t)stage * STAGE_BYTES;
        const uint32_t bS = aS + TILE_HALVES * 2;
#pragma unroll
        for (int i = 0; i < 8; i++) {
            const int c   = tid + 128 * i;     // 1024 chunks of 8 halves per tile
            const int row = c >> 3;
            const int c16 = (c & 7) * 8;
            cp16(aS + (uint32_t)(row * AST + c16) * 2, Ab + (long)(m0 + row) * K + k0 + c16);
            cp16(bS + (uint32_t)(row * AST + c16) * 2, Bb + (long)(n0 + row) * K + k0 + c16);
        }
    };

    float acc[4][8][4];
#pragma unroll
    for (int mt = 0; mt < 4; mt++)
#pragma unroll
        for (int nt = 0; nt < 8; nt++)
#pragma unroll
            for (int i = 0; i < 4; i++) acc[mt][nt][i] = 0.0f;

    const int KT = K / BK;
#pragma unroll
    for (int s = 0; s < STAGES; s++) {
        if (s < KT) { load_tiles(s, s * BK); cp_commit(); }
    }

    uint32_t afr[2][4][4], bfr[2][4][4];

    for (int t = 0; t < KT; t++) {
        const int rem = KT - 1 - t;
        if (rem >= 2)      asm volatile("cp.async.wait_group 2;");
        else if (rem == 1) asm volatile("cp.async.wait_group 1;");
        else               asm volatile("cp.async.wait_group 0;");
        __syncthreads();

        const int stage = t % STAGES;
        const uint32_t aS = smBase + (uint32_t)stage * STAGE_BYTES;
        const uint32_t bS = aS + TILE_HALVES * 2;

        // prefetch fragments for k16 step 0
#pragma unroll
        for (int mt = 0; mt < 4; mt++)
            ldsm4(afr[0][mt], aS + (uint32_t)((wm + mt * 16) * AST + aLane) * 2);
#pragma unroll
        for (int ng = 0; ng < 4; ng++)
            ldsm4(bfr[0][ng], bS + (uint32_t)((wn + ng * 16) * AST + bLane) * 2);

#pragma unroll
        for (int ks = 0; ks < BK / 16; ks++) {
            const int cur = ks & 1;
            const int nxt = cur ^ 1;
            if (ks < BK / 16 - 1) {
                const int k16 = (ks + 1) * 16;
#pragma unroll
                for (int mt = 0; mt < 4; mt++)
                    ldsm4(afr[nxt][mt], aS + (uint32_t)((wm + mt * 16) * AST + k16 + aLane) * 2);
#pragma unroll
                for (int ng = 0; ng < 4; ng++)
                    ldsm4(bfr[nxt][ng], bS + (uint32_t)((wn + ng * 16) * AST + k16 + bLane) * 2);
            }
#pragma unroll
            for (int mt = 0; mt < 4; mt++)
#pragma unroll
                for (int nt = 0; nt < 8; nt++)
                    mma_f16(acc[mt][nt], afr[cur][mt], &bfr[cur][nt >> 1][(nt & 1) * 2]);
        }
        __syncthreads();

        if (t + STAGES < KT) { load_tiles(stage, (t + STAGES) * BK); cp_commit(); }
    }

    // epilogue
#pragma unroll
    for (int mt = 0; mt < 4; mt++) {
        const long row0 = m0 + wm + mt * 16 + r;
#pragma unroll
        for (int nt = 0; nt < 8; nt++) {
            const int colb = n0 + wn + nt * 8 + 2 * cc;
            float x0 = acc[mt][nt][0] * alpha;
            float x1 = acc[mt][nt][1] * alpha;
            float x2 = acc[mt][nt][2] * alpha;
            float x3 = acc[mt][nt][3] * alpha;
            if (HAS_BIAS) {
                const float b0 = bias[colb], b1 = bias[colb + 1];
                x0 += b0; x1 += b1; x2 += b0; x3 += b1;
            }
            if (OUT_HALF) {
                __half* Cb = (__half*)Cv + (long)blockIdx.z * sCz;
                *(__half2*)(Cb + row0 * N + colb)       = __floats2half2_rn(x0, x1);
                *(__half2*)(Cb + (row0 + 8) * N + colb) = __floats2half2_rn(x2, x3);
            } else {
                float* Cb = (float*)Cv + (long)blockIdx.z * sCz;
                *(float2*)(Cb + row0 * N + colb)       = make_float2(x0, x1);
                *(float2*)(Cb + (row0 + 8) * N + colb) = make_float2(x2, x3);
            }
        }
    }
}

// ---------------------------------------------------------------------------
// Batched fp32 -> fp16(rn): z selects which of 3 arrays
// ---------------------------------------------------------------------------
__global__ __launch_bounds__(256)
void f2h3_kernel(const float* __restrict__ a0, const float* __restrict__ a1,
                 const float* __restrict__ a2, __half* __restrict__ o0,
                 __half* __restrict__ o1, __half* __restrict__ o2, long n4)
{
    const float* in = (blockIdx.z == 0) ? a0 : (blockIdx.z == 1) ? a1 : a2;
    __half* out     = (blockIdx.z == 0) ? o0 : (blockIdx.z == 1) ? o1 : o2;
    long i = (long)blockIdx.x * blockDim.x + threadIdx.x;
    const long stride = (long)gridDim.x * blockDim.x;
    for (; i < n4; i += stride) {
        float4 v = ((const float4*)in)[i];
        __half2* o = (__half2*)(out + i * 4);
        o[0] = __floats2half2_rn(v.x, v.y);
        o[1] = __floats2half2_rn(v.z, v.w);
    }
}

// ---------------------------------------------------------------------------
// Batched transpose + convert: W f32 [K][N] -> half [N][K] (z selects weight)
// ---------------------------------------------------------------------------
__global__ __launch_bounds__(256)
void wtrans3_kernel(const float* __restrict__ a0, const float* __restrict__ a1,
                    const float* __restrict__ a2, __half* __restrict__ o0,
                    __half* __restrict__ o1, __half* __restrict__ o2)
{
    const float* in = (blockIdx.z == 0) ? a0 : (blockIdx.z == 1) ? a1 : a2;
    __half* out     = (blockIdx.z == 0) ? o0 : (blockIdx.z == 1) ? o1 : o2;
    __shared__ float t[32][33];
    const int bx = blockIdx.x * 32;   // n
    const int by = blockIdx.y * 32;   // k
    const int tx = threadIdx.x, ty = threadIdx.y;
#pragma unroll
    for (int i = ty; i < 32; i += 8)
        t[i][tx] = in[(long)(by + i) * DD + bx + tx];
    __syncthreads();
#pragma unroll
    for (int i = ty; i < 32; i += 8)
        out[(long)(bx + i) * DD + by + tx] = __float2half_rn(t[tx][i]);
}

// ---------------------------------------------------------------------------
// Half transpose (batched): in [rows][cols] -> out [cols][rows]
// ---------------------------------------------------------------------------
__global__ __launch_bounds__(256)
void htrans_kernel(const __half* __restrict__ in, __half* __restrict__ out,
                   int rows, int cols)
{
    __shared__ __half t[32][34];
    const int bx = blockIdx.x * 32;   // col
    const int by = blockIdx.y * 32;   // row
    const int tx = threadIdx.x, ty = threadIdx.y;
    const __half* ib = in  + (long)blockIdx.z * rows * cols;
    __half*       ob = out + (long)blockIdx.z * rows * cols;
#pragma unroll
    for (int i = ty; i < 32; i += 8)
        t[i][tx] = ib[(long)(by + i) * cols + bx + tx];
    __syncthreads();
#pragma unroll
    for (int i = ty; i < 32; i += 8)
        ob[(long)(bx + i) * rows + by + tx] = t[tx][i];
}

// ---------------------------------------------------------------------------
// Row softmax over 2048 fp32 cols -> fp16 probabilities
// ---------------------------------------------------------------------------
__global__ __launch_bounds__(256)
void softmax2048_h(const float* __restrict__ S, __half* __restrict__ P)
{
    const float* row = S + (long)blockIdx.x * SS;
    __half*      po  = P + (long)blockIdx.x * SS;
    const int t = threadIdx.x;

    float v[8];
    float mx = -1e30f;
#pragma unroll
    for (int i = 0; i < 8; i++) {
        v[i] = row[t + i * 256];
        mx = fmaxf(mx, v[i]);
    }
#pragma unroll
    for (int o = 16; o > 0; o >>= 1)
        mx = fmaxf(mx, __shfl_xor_sync(0xFFFFFFFFu, mx, o));

    __shared__ float red[8];
    if ((t & 31) == 0) red[t >> 5] = mx;
    __syncthreads();
    float bmax = red[0];
#pragma unroll
    for (int i = 1; i < 8; i++) bmax = fmaxf(bmax, red[i]);
    __syncthreads();

    float sum = 0.0f;
#pragma unroll
    for (int i = 0; i < 8; i++) {
        v[i] = __expf(v[i] - bmax);
        sum += v[i];
    }
#pragma unroll
    for (int o = 16; o > 0; o >>= 1)
        sum += __shfl_xor_sync(0xFFFFFFFFu, sum, o);
    if ((t & 31) == 0) red[t >> 5] = sum;
    __syncthreads();
    float tot = 0.0f;
#pragma unroll
    for (int i = 0; i < 8; i++) tot += red[i];

    const float inv = __frcp_rn(tot);
#pragma unroll
    for (int i = 0; i < 8; i++)
        po[t + i * 256] = __float2half_rn(v[i] * inv);
}

// ---------------------------------------------------------------------------
extern "C" void kernel_launch(void* const* d_in, const int* in_sizes, int n_in,
                              void* d_out, int out_size)
{
    const float* q  = (const float*)d_in[0];
    const float* k  = (const float*)d_in[1];
    const float* v  = (const float*)d_in[2];
    const float* Wq = (const float*)d_in[3];
    const float* bq = (const float*)d_in[4];
    const float* Wk = (const float*)d_in[5];
    const float* bk = (const float*)d_in[6];
    const float* Wv = (const float*)d_in[7];
    const float* bv = (const float*)d_in[8];
    float* out = (float*)d_out;

    __half *qh, *kh, *vh, *WqT, *WkT, *WvT, *Qp, *Kp, *Vp, *VpT, *Ph;
    float *Sc;
    cudaGetSymbolAddress((void**)&qh,  g_qh);
    cudaGetSymbolAddress((void**)&kh,  g_kh);
    cudaGetSymbolAddress((void**)&vh,  g_vh);
    cudaGetSymbolAddress((void**)&WqT, g_WqT);
    cudaGetSymbolAddress((void**)&WkT, g_WkT);
    cudaGetSymbolAddress((void**)&WvT, g_WvT);
    cudaGetSymbolAddress((void**)&Qp,  g_Qp);
    cudaGetSymbolAddress((void**)&Kp,  g_Kp);
    cudaGetSymbolAddress((void**)&Vp,  g_Vp);
    cudaGetSymbolAddress((void**)&VpT, g_VpT);
    cudaGetSymbolAddress((void**)&Sc,  g_Sc);
    cudaGetSymbolAddress((void**)&Ph,  g_Ph);

    cudaFuncSetAttribute(hgemm_tn<true,  true >, cudaFuncAttributeMaxDynamicSharedMemorySize, GEMM_SMEM);
    cudaFuncSetAttribute(hgemm_tn<false, false>, cudaFuncAttributeMaxDynamicSharedMemorySize, GEMM_SMEM);

    const long nQKV = (long)BB * SS * DD;

    // 1: convert q/k/v to fp16 (one launch, grid.z = 3)
    {
        dim3 g(1024, 1, 3);
        f2h3_kernel<<<g, 256>>>(q, k, v, qh, kh, vh, nQKV / 4);
    }
    // 2: transpose+convert weights (one launch, grid.z = 3)
    {
        dim3 g(32, 32, 3), b(32, 8);
        wtrans3_kernel<<<g, b>>>(Wq, Wk, Wv, WqT, WkT, WvT);
    }

    const dim3 blk(128);

    // 3-5: Projections (TN, bias, half out): M=8192, N=1024, K=1024
    {
        dim3 g(DD / 128, (BB * SS) / 128, 1);
        hgemm_tn<true, true><<<g, blk, GEMM_SMEM>>>(qh, WqT, bq, Qp, DD, DD, 1.0f, 0, 0, 0);
        hgemm_tn<true, true><<<g, blk, GEMM_SMEM>>>(kh, WkT, bk, Kp, DD, DD, 1.0f, 0, 0, 0);
        hgemm_tn<true, true><<<g, blk, GEMM_SMEM>>>(vh, WvT, bv, Vp, DD, DD, 1.0f, 0, 0, 0);
    }

    // 6: Scores (TN, f32 out): per batch M=N=2048, K=1024, alpha=1/32
    //    (6th launch — ncu -s 5 -c 1 profiles this one)
    {
        dim3 g(SS / 128, SS / 128, BB);
        hgemm_tn<false, false><<<g, blk, GEMM_SMEM>>>(Qp, Kp, nullptr, Sc,
                                                      SS, DD, 0.03125f,
                                                      (long)SS * DD, (long)SS * DD, (long)SS * SS);
    }

    // 7: Softmax (f32 -> f16 probs)
    softmax2048_h<<<BB * SS, 256>>>(Sc, Ph);

    // 8: transpose Vp per batch: [S][D] -> [D][S]  (needed only by PV)
    {
        dim3 g(DD / 32, SS / 32, BB), b(32, 8);
        htrans_kernel<<<g, b>>>(Vp, VpT, SS, DD);
    }

    // 9: PV (TN, f32 out): A=Ph [S,S], B=VpT [D][S]; M=2048, N=1024, K=2048
    {
        dim3 g(DD / 128, SS / 128, BB);
        hgemm_tn<false, false><<<g, blk, GEMM_SMEM>>>(Ph, VpT, nullptr, out,
                                                      DD, SS, 1.0f,
                                                      (long)SS * SS, (long)SS * DD, (long)SS * DD);
    }
}